// round 5
// baseline (speedup 1.0000x reference)
#include <cuda_runtime.h>
#include <cstdint>

// PatchEmbed permute: x[16,64,256,256] f32 -> out[16, 64*64, 64*4*4]
// out[n, wp, hp, c, pi, pj] = x[n, c, hp*4+pi, wp*4+pj]
// pj (4 floats) => float4 units. Per (n, hp): transpose M[cp=256][wp=64]
// of float4 where cp = c*4+pi.
//   input  f4 idx = ((n*64 + c)*256 + hp*4 + pi)*64 + wp
//   output f4 idx = ((n*64 + wp)*64 + hp)*256 + cp
//
// R5: 2-stage cp.async double-buffered pipeline over 4 hp-tiles per block.
// Stage tile = 16(cp) x 64(wp) f4 = 16KB; 2 stages = 32KB smem -> still
// 4 blocks x 16 warps = 64 warps/SM. Reads for tile i+1 stay in flight while
// tile i is being stored -> steadier HBM read/write mix.

#define N_ 16
#define C_ 64
#define HP_ 64
#define WP_ 64
#define CP_ 256
#define CPT_ 16            // cp per tile
#define HPB_ 4             // hp tiles per block
#define THREADS 512
#define NDATA    (N_ * C_ * 256 * 256)

__global__ __launch_bounds__(THREADS, 4)
void patch_permute_kernel(const float4* __restrict__ in, float4* __restrict__ out,
                          int tail_count) {
    __shared__ float4 tile[2][CPT_][WP_];   // 2 x 16KB, XOR-swizzled

    const int cpt = blockIdx.x;    // 0..15  (cp tile: cp in [cpt*16, cpt*16+16))
    const int hpy = blockIdx.y;    // 0..15  (hp in [hpy*4, hpy*4+4))
    const int n   = blockIdx.z;    // 0..15
    const int tid = threadIdx.x;

    // ---- fused tail write (ori_shape = 16,64,256,256), one block only ----
    if (cpt == 0 && hpy == 0 && n == 0 && tid < 4 && tid < tail_count) {
        const float vals[4] = {16.0f, 64.0f, 256.0f, 256.0f};
        ((float*)out)[NDATA + tid] = vals[tid];
    }

    // per-thread fill coords (2 f4 per thread per tile)
    //   idx = i*512+tid ; cpl = idx>>6 (0..15) ; wp = idx&63
    // per-thread store coords
    //   idx = i*512+tid ; wp = idx>>4 (0..63)  ; cpl = idx&15

#define FILL(IT, BUF)                                                          \
    {                                                                          \
        int hp = hpy * HPB_ + (IT);                                            \
        _Pragma("unroll")                                                      \
        for (int i = 0; i < (CPT_ * WP_) / THREADS; i++) {                     \
            int idx = i * THREADS + tid;                                       \
            int cpl = idx >> 6;                                                \
            int wp  = idx & 63;                                                \
            int cp  = cpt * CPT_ + cpl;                                        \
            int c   = cp >> 2;                                                 \
            int pi  = cp & 3;                                                  \
            int in_idx = ((n * C_ + c) * 256 + hp * 4 + pi) * WP_ + wp;        \
            uint32_t saddr = (uint32_t)__cvta_generic_to_shared(               \
                &tile[BUF][cpl][wp ^ (cpl & 7)]);                              \
            asm volatile("cp.async.cg.shared.global [%0], [%1], 16;\n"         \
                         :: "r"(saddr), "l"(in + in_idx) : "memory");          \
        }                                                                      \
        asm volatile("cp.async.commit_group;\n" ::: "memory");                 \
    }

#define STORE(IT, BUF)                                                         \
    {                                                                          \
        int hp = hpy * HPB_ + (IT);                                            \
        _Pragma("unroll")                                                      \
        for (int i = 0; i < (CPT_ * WP_) / THREADS; i++) {                     \
            int idx = i * THREADS + tid;                                       \
            int wp  = idx >> 4;                                                \
            int cpl = idx & 15;                                                \
            int cp  = cpt * CPT_ + cpl;                                        \
            int out_idx = ((n * WP_ + wp) * HP_ + hp) * CP_ + cp;              \
            out[out_idx] = tile[BUF][cpl][wp ^ (cpl & 7)];                     \
        }                                                                      \
    }

    FILL(0, 0)
#pragma unroll
    for (int it = 0; it < HPB_; it++) {
        if (it + 1 < HPB_) {
            if ((it + 1) & 1) FILL(it + 1, 1) else FILL(it + 1, 0)
        }
        if (it + 1 < HPB_)
            asm volatile("cp.async.wait_group 1;\n" ::: "memory");
        else
            asm volatile("cp.async.wait_group 0;\n" ::: "memory");
        __syncthreads();
        if (it & 1) STORE(it, 1) else STORE(it, 0)
        __syncthreads();   // buf reuse fence for fill at it+2
    }
}

extern "C" void kernel_launch(void* const* d_in, const int* in_sizes, int n_in,
                              void* d_out, int out_size) {
    (void)in_sizes; (void)n_in;
    const float4* in  = (const float4*)d_in[0];
    float4*       out = (float4*)d_out;

    int tail_count = out_size > NDATA ? (out_size - NDATA) : 0;

    dim3 grid(CP_ / CPT_, HP_ / HPB_, N_);   // 16 x 16 x 16 = 4096 blocks
    patch_permute_kernel<<<grid, THREADS>>>(in, out, tail_count);
}